// round 14
// baseline (speedup 1.0000x reference)
#include <cuda_runtime.h>
#include <cuda_fp16.h>
#include <cstdint>

#define N_NODES 100000
#define MAX_EDGES 1700000
#define D 128
#define SCAN_BLK 1024

// ---------------- scratch ----------------
// h stored as fp16 (unscaled xW^T): row = 128 halfs = 256B = 32 uint2
__device__ uint2  g_gh[(size_t)N_NODES * 32];
__device__ float  g_dinv[N_NODES];                   // rsqrt(deg+1)
__device__ int    g_deg[N_NODES];                    // in-degree per dst (zeroed by agg)
__device__ int    g_off[N_NODES];                    // CSR exclusive offsets
__device__ int    g_cur[N_NODES];                    // scatter cursors
__device__ int    g_csr[MAX_EDGES];                  // src index per CSR slot
__device__ unsigned long long g_stat[128];           // lookback: flag(hi32)|sum(lo32)

#define FLAG_A 1ull
#define FLAG_P 2ull

// ---------------- helpers ----------------
__device__ __forceinline__ int block_detect_is64(const int* ei32) {
    int nz = 0;
    if (threadIdx.x < 64) nz = (ei32[2 * threadIdx.x + 1] != 0);
    return !__syncthreads_or(nz);
}

__device__ __forceinline__ void mma16816(float* c,
    unsigned a0, unsigned a1, unsigned a2, unsigned a3,
    unsigned b0, unsigned b1)
{
    asm volatile(
        "mma.sync.aligned.m16n8k16.row.col.f32.f16.f16.f32 "
        "{%0,%1,%2,%3}, {%4,%5,%6,%7}, {%8,%9}, {%0,%1,%2,%3};"
        : "+f"(c[0]), "+f"(c[1]), "+f"(c[2]), "+f"(c[3])
        : "r"(a0), "r"(a1), "r"(a2), "r"(a3), "r"(b0), "r"(b1));
}

// ---------------- kernels ----------------
// deg: 2 edges/thread; block 0 also resets the scan status array (runs
// stream-ordered before scan_kernel).
__global__ void deg_kernel(const void* __restrict__ ei, int E) {
    if (blockIdx.x == 0 && threadIdx.x < 128) g_stat[threadIdx.x] = 0ull;
    int is64 = block_detect_is64((const int*)ei);
    int i0 = (blockIdx.x * blockDim.x + threadIdx.x) * 2;
    if (i0 >= E) return;
    int d0, d1 = -1;
    if (is64) {
        const long long* p = (const long long*)ei + E;   // dst row
        if (i0 + 1 < E) {
            longlong2 v = *(const longlong2*)(p + i0);
            d0 = (int)v.x; d1 = (int)v.y;
        } else d0 = (int)p[i0];
    } else {
        const int* p = (const int*)ei + E;
        if (i0 + 1 < E) {
            int2 v = *(const int2*)(p + i0);
            d0 = v.x; d1 = v.y;
        } else d0 = p[i0];
    }
    if ((unsigned)d0 < (unsigned)N_NODES) atomicAdd(&g_deg[d0], 1);
    if (d1 >= 0 && (unsigned)d1 < (unsigned)N_NODES) atomicAdd(&g_deg[d1], 1);
}

// Single-kernel exclusive scan with decoupled lookback.
// All NB (<=98) blocks are co-resident (1024 thr, 148 SMs) -> no deadlock.
__global__ __launch_bounds__(SCAN_BLK) void scan_kernel(int n) {
    __shared__ int sh[SCAN_BLK];
    __shared__ int s_excl;
    const int t = threadIdx.x;
    const int b = blockIdx.x;
    const int i = b * SCAN_BLK + t;
    int v = (i < n) ? g_deg[i] : 0;
    sh[t] = v;
    __syncthreads();
#pragma unroll
    for (int o = 1; o < SCAN_BLK; o <<= 1) {
        int add = (t >= o) ? sh[t - o] : 0;
        __syncthreads();
        sh[t] += add;
        __syncthreads();
    }
    int incl = sh[t];
    int total = sh[SCAN_BLK - 1];

    // publish local aggregate (block 0 publishes final prefix directly)
    if (t == 0) {
        unsigned long long flag = (b == 0) ? FLAG_P : FLAG_A;
        atomicExch(&g_stat[b], (flag << 32) | (unsigned)total);
    }

    // warp 0 lookback for b > 0
    if (b > 0) {
        if (t < 32) {
            int excl = 0;
            int look = b - 1;
            while (true) {
                int idx = look - t;
                unsigned long long st;
                if (idx >= 0) st = atomicAdd(&g_stat[idx], 0ull);
                else          st = (FLAG_P << 32);              // virtual P=0
                unsigned flag = (unsigned)(st >> 32);
                unsigned valid = __ballot_sync(0xffffffffu, flag != 0);
                if (valid != 0xffffffffu) continue;             // retry window
                unsigned maskp = __ballot_sync(0xffffffffu, flag == (unsigned)FLAG_P);
                int val = (int)(unsigned)(st & 0xffffffffull);
                if (maskp) {
                    int lp = __ffs(maskp) - 1;                  // nearest P
                    int contrib = (t <= lp) ? val : 0;
#pragma unroll
                    for (int o = 16; o; o >>= 1)
                        contrib += __shfl_xor_sync(0xffffffffu, contrib, o);
                    excl += contrib;
                    break;
                } else {
                    int contrib = val;
#pragma unroll
                    for (int o = 16; o; o >>= 1)
                        contrib += __shfl_xor_sync(0xffffffffu, contrib, o);
                    excl += contrib;
                    look -= 32;
                }
            }
            if (t == 0) {
                s_excl = excl;
                atomicExch(&g_stat[b], (FLAG_P << 32) | (unsigned)(excl + total));
            }
        }
    } else if (t == 0) {
        s_excl = 0;
    }
    __syncthreads();

    if (i < n) {
        int o = s_excl + incl - v;        // exclusive
        g_off[i] = o;
        g_cur[i] = o;
        g_dinv[i] = rsqrtf((float)g_deg[i] + 1.0f);
    }
}

// ---------------- scatter edges into CSR (by dst), 2 edges/thread ----------
__global__ void csr_kernel(const void* __restrict__ ei, int E) {
    int is64 = block_detect_is64((const int*)ei);
    int i0 = (blockIdx.x * blockDim.x + threadIdx.x) * 2;
    if (i0 >= E) return;
    int s0, d0, s1 = -1, d1 = -1;
    if (is64) {
        const long long* ps = (const long long*)ei;
        const long long* pd = ps + E;
        if (i0 + 1 < E) {
            longlong2 vs = *(const longlong2*)(ps + i0);
            longlong2 vd = *(const longlong2*)(pd + i0);
            s0 = (int)vs.x; s1 = (int)vs.y;
            d0 = (int)vd.x; d1 = (int)vd.y;
        } else { s0 = (int)ps[i0]; d0 = (int)pd[i0]; }
    } else {
        const int* ps = (const int*)ei;
        const int* pd = ps + E;
        if (i0 + 1 < E) {
            int2 vs = *(const int2*)(ps + i0);
            int2 vd = *(const int2*)(pd + i0);
            s0 = vs.x; s1 = vs.y;
            d0 = vd.x; d1 = vd.y;
        } else { s0 = ps[i0]; d0 = pd[i0]; }
    }
    if ((unsigned)s0 < (unsigned)N_NODES && (unsigned)d0 < (unsigned)N_NODES) {
        int pos = atomicAdd(&g_cur[d0], 1);
        g_csr[pos] = s0;
    }
    if (s1 >= 0 && (unsigned)s1 < (unsigned)N_NODES && (unsigned)d1 < (unsigned)N_NODES) {
        int pos = atomicAdd(&g_cur[d1], 1);
        g_csr[pos] = s1;
    }
}

// ---------------- HMMA GEMM: h = fp16( x @ W^T ) (independent of edges) ----
#define GBM 128
#define GKT 32
#define ST 40   // smem row stride in halfs (bank-permuting)
__global__ __launch_bounds__(256) void gemm_mma_kernel(
    const float* __restrict__ x, const float* __restrict__ W, int N)
{
    __shared__ __half xs[GBM][ST];   // x fp16 [m][k]
    __shared__ __half wh[D][ST];     // W hi   [n][k]
    __shared__ __half wl[D][ST];     // W lo   [n][k]

    const int tid = threadIdx.x;
    const int warpId = tid >> 5;
    const int lane = tid & 31;
    const int rowBase = blockIdx.x * GBM;
    const int warpRow = warpId * 16;
    const int qr = lane >> 2;        // 0..7
    const int qc = (lane & 3) * 2;   // 0,2,4,6

    float c[16][4];
#pragma unroll
    for (int t = 0; t < 16; t++)
#pragma unroll
        for (int j = 0; j < 4; j++) c[t][j] = 0.0f;

    for (int kt = 0; kt < D; kt += GKT) {
#pragma unroll
        for (int it = 0; it < 4; it++) {
            int i = tid + it * 256;           // 0..1023 float4 slots
            int m = i >> 3;
            int kq = i & 7;
            float4 v = make_float4(0.f, 0.f, 0.f, 0.f);
            int row = rowBase + m;
            if (row < N)
                v = *(const float4*)(x + (size_t)row * D + kt + kq * 4);
            __half2 p0 = __floats2half2_rn(v.x, v.y);
            __half2 p1 = __floats2half2_rn(v.z, v.w);
            *(__half2*)&xs[m][kq * 4]     = p0;
            *(__half2*)&xs[m][kq * 4 + 2] = p1;
        }
#pragma unroll
        for (int it = 0; it < 4; it++) {
            int i = tid + it * 256;
            int n = i >> 3;
            int kq = i & 7;
            float4 v = *(const float4*)(W + (size_t)n * D + kt + kq * 4);
            __half hx = __float2half_rn(v.x);
            __half hy = __float2half_rn(v.y);
            __half hz = __float2half_rn(v.z);
            __half hw = __float2half_rn(v.w);
            __half lx = __float2half_rn(v.x - __half2float(hx));
            __half ly = __float2half_rn(v.y - __half2float(hy));
            __half lz = __float2half_rn(v.z - __half2float(hz));
            __half lw = __float2half_rn(v.w - __half2float(hw));
            *(__half2*)&wh[n][kq * 4]     = __halves2half2(hx, hy);
            *(__half2*)&wh[n][kq * 4 + 2] = __halves2half2(hz, hw);
            *(__half2*)&wl[n][kq * 4]     = __halves2half2(lx, ly);
            *(__half2*)&wl[n][kq * 4 + 2] = __halves2half2(lz, lw);
        }
        __syncthreads();

#pragma unroll
        for (int k0 = 0; k0 < GKT; k0 += 16) {
            int ar = warpRow + qr;
            int ac = k0 + qc;
            unsigned a0 = *(const unsigned*)&xs[ar][ac];
            unsigned a1 = *(const unsigned*)&xs[ar + 8][ac];
            unsigned a2 = *(const unsigned*)&xs[ar][ac + 8];
            unsigned a3 = *(const unsigned*)&xs[ar + 8][ac + 8];
#pragma unroll
            for (int t = 0; t < 16; t++) {
                int bn = t * 8 + qr;
                unsigned bh0 = *(const unsigned*)&wh[bn][ac];
                unsigned bh1 = *(const unsigned*)&wh[bn][ac + 8];
                unsigned bl0 = *(const unsigned*)&wl[bn][ac];
                unsigned bl1 = *(const unsigned*)&wl[bn][ac + 8];
                mma16816(c[t], a0, a1, a2, a3, bh0, bh1);
                mma16816(c[t], a0, a1, a2, a3, bl0, bl1);
            }
        }
        __syncthreads();
    }

    int r0 = rowBase + warpRow + qr;
    int r1 = r0 + 8;
    unsigned* gout = (unsigned*)g_gh;          // 64 half2 per row
#pragma unroll
    for (int t = 0; t < 16; t++) {
        int colp = t * 4 + (lane & 3);         // half2 index within row
        if (r0 < N) {
            __half2 h = __floats2half2_rn(c[t][0], c[t][1]);
            gout[(size_t)r0 * 64 + colp] = *(unsigned*)&h;
        }
        if (r1 < N) {
            __half2 h = __floats2half2_rn(c[t][2], c[t][3]);
            gout[(size_t)r1 * 64 + colp] = *(unsigned*)&h;
        }
    }
}

// ---------------- aggregate + epilogue: warp per node, MLP=8, fp16 gather ----
// acc = dinv_w*h_w + sum dinv_s*h_s ; out = relu(dinv_w*acc + b)
// Also zeroes g_deg[w] for the next graph replay (self-cleaning histogram).
__device__ __forceinline__ void acc_u2s(float& a0, float& a1, float& a2, float& a3,
                                        uint2 u, float s) {
    float2 p = __half22float2(*(__half2*)&u.x);
    float2 q = __half22float2(*(__half2*)&u.y);
    a0 = fmaf(p.x, s, a0); a1 = fmaf(p.y, s, a1);
    a2 = fmaf(q.x, s, a2); a3 = fmaf(q.y, s, a3);
}

__global__ __launch_bounds__(256) void agg_kernel(
    const float* __restrict__ b, float* __restrict__ out, int N)
{
    int w = (blockIdx.x * blockDim.x + threadIdx.x) >> 5;
    int lane = threadIdx.x & 31;
    if (w >= N) return;

    int deg = g_deg[w];
    if (lane == 0) g_deg[w] = 0;          // reset for next replay
    int e = g_off[w];
    float dinv = g_dinv[w];

    float a0 = 0.f, a1 = 0.f, a2 = 0.f, a3 = 0.f;
    acc_u2s(a0, a1, a2, a3, g_gh[(size_t)w * 32 + lane], dinv);  // self loop

    int cnt = deg;
    while (cnt >= 8) {
        int s[8];
#pragma unroll
        for (int u = 0; u < 8; u++) s[u] = __ldg(&g_csr[e + u]);
        uint2 v[8];
        float ds[8];
#pragma unroll
        for (int u = 0; u < 8; u++) {
            v[u] = g_gh[(size_t)s[u] * 32 + lane];
            ds[u] = __ldg(&g_dinv[s[u]]);
        }
#pragma unroll
        for (int u = 0; u < 8; u++) acc_u2s(a0, a1, a2, a3, v[u], ds[u]);
        e += 8; cnt -= 8;
    }
    if (cnt >= 4) {
        int s0 = __ldg(&g_csr[e + 0]);
        int s1 = __ldg(&g_csr[e + 1]);
        int s2 = __ldg(&g_csr[e + 2]);
        int s3 = __ldg(&g_csr[e + 3]);
        uint2 v0 = g_gh[(size_t)s0 * 32 + lane];
        uint2 v1 = g_gh[(size_t)s1 * 32 + lane];
        uint2 v2 = g_gh[(size_t)s2 * 32 + lane];
        uint2 v3 = g_gh[(size_t)s3 * 32 + lane];
        float d0 = __ldg(&g_dinv[s0]);
        float d1 = __ldg(&g_dinv[s1]);
        float d2 = __ldg(&g_dinv[s2]);
        float d3 = __ldg(&g_dinv[s3]);
        acc_u2s(a0, a1, a2, a3, v0, d0);
        acc_u2s(a0, a1, a2, a3, v1, d1);
        acc_u2s(a0, a1, a2, a3, v2, d2);
        acc_u2s(a0, a1, a2, a3, v3, d3);
        e += 4; cnt -= 4;
    }
    while (cnt > 0) {
        int s = __ldg(&g_csr[e]);
        acc_u2s(a0, a1, a2, a3, g_gh[(size_t)s * 32 + lane], __ldg(&g_dinv[s]));
        e++; cnt--;
    }

    float4 bb = *(const float4*)(b + lane * 4);
    float4 o;
    o.x = fmaxf(fmaf(a0, dinv, bb.x), 0.0f);
    o.y = fmaxf(fmaf(a1, dinv, bb.y), 0.0f);
    o.z = fmaxf(fmaf(a2, dinv, bb.z), 0.0f);
    o.w = fmaxf(fmaf(a3, dinv, bb.w), 0.0f);
    *(float4*)(out + (size_t)w * D + lane * 4) = o;
}

// ---------------- launch ----------------
extern "C" void kernel_launch(void* const* d_in, const int* in_sizes, int n_in,
                              void* d_out, int out_size)
{
    const float* x  = (const float*)d_in[0];
    const void*  ei = d_in[1];                 // [2, E], int64 OR int32 (detected)
    const float* W  = (const float*)d_in[2];
    const float* b  = (const float*)d_in[3];
    float* out = (float*)d_out;

    const int N = in_sizes[0] / D;
    const int E = in_sizes[1] / 2;
    const int NB = (N + SCAN_BLK - 1) / SCAN_BLK;
    const int E2 = (E + 1) / 2;

    static cudaStream_t s2 = nullptr;
    static cudaEvent_t evFork = nullptr, evJoin = nullptr;
    if (s2 == nullptr) {
        cudaStreamCreateWithFlags(&s2, cudaStreamNonBlocking);
        cudaEventCreateWithFlags(&evFork, cudaEventDisableTiming);
        cudaEventCreateWithFlags(&evJoin, cudaEventDisableTiming);
    }

    // Fork: GEMM (depends only on x, W) overlaps the edge chain.
    cudaEventRecord(evFork, 0);
    cudaStreamWaitEvent(s2, evFork, 0);
    gemm_mma_kernel<<<(N + GBM - 1) / GBM, 256, 0, s2>>>(x, W, N);
    cudaEventRecord(evJoin, s2);

    // Edge chain on the main (capture) stream.
    deg_kernel<<<(E2 + 255) / 256, 256>>>(ei, E);
    scan_kernel<<<NB, SCAN_BLK>>>(N);
    csr_kernel<<<(E2 + 255) / 256, 256>>>(ei, E);

    // Join, then aggregate.
    cudaStreamWaitEvent(0, evJoin, 0);
    agg_kernel<<<(N * 32 + 255) / 256, 256>>>(b, out, N);
}

// round 15
// speedup vs baseline: 3.4242x; 3.4242x over previous
#include <cuda_runtime.h>
#include <cuda_fp16.h>
#include <cstdint>

#define N_NODES 100000
#define MAX_EDGES 1700000
#define D 128
#define SCAN_BLK 1024

// ---------------- scratch ----------------
// g stored as fp16 (dinv-scaled xW^T): row = 128 halfs = 256B = 32 uint2
__device__ uint2  g_gh[(size_t)N_NODES * 32];
__device__ int    g_deg[N_NODES];                    // in-degree per dst (edges only)
__device__ int    g_off[N_NODES];                    // CSR exclusive offsets
__device__ int    g_cur[N_NODES];                    // scatter cursors
__device__ int    g_csr[MAX_EDGES];                  // src index per CSR slot
__device__ int    g_bsum[128];                       // per-block scan sums

// ---------------- helpers ----------------
__device__ __forceinline__ int block_detect_is64(const int* ei32) {
    int nz = 0;
    if (threadIdx.x < 64) nz = (ei32[2 * threadIdx.x + 1] != 0);
    return !__syncthreads_or(nz);
}

__device__ __forceinline__ void mma16816(float* c,
    unsigned a0, unsigned a1, unsigned a2, unsigned a3,
    unsigned b0, unsigned b1)
{
    asm volatile(
        "mma.sync.aligned.m16n8k16.row.col.f32.f16.f16.f32 "
        "{%0,%1,%2,%3}, {%4,%5,%6,%7}, {%8,%9}, {%0,%1,%2,%3};"
        : "+f"(c[0]), "+f"(c[1]), "+f"(c[2]), "+f"(c[3])
        : "r"(a0), "r"(a1), "r"(a2), "r"(a3), "r"(b0), "r"(b1));
}

// ---------------- kernels ----------------
__global__ void zero_deg_kernel(int n) {
    int i = blockIdx.x * blockDim.x + threadIdx.x;
    if (i < n) g_deg[i] = 0;
}

__global__ void deg_kernel(const void* __restrict__ ei, int E) {
    int is64 = block_detect_is64((const int*)ei);
    int i = blockIdx.x * blockDim.x + threadIdx.x;
    if (i >= E) return;
    int d;
    if (is64) d = (int)((const long long*)ei)[(size_t)E + i];
    else      d = ((const int*)ei)[(size_t)E + i];
    if ((unsigned)d < (unsigned)N_NODES) atomicAdd(&g_deg[d], 1);
}

// ---------------- exclusive scan of g_deg -> g_off (2 kernels, coalesced) ----
__global__ void scan1_kernel(int n) {
    __shared__ int sh[SCAN_BLK];
    int t = threadIdx.x;
    int i = blockIdx.x * SCAN_BLK + t;
    int v = (i < n) ? g_deg[i] : 0;
    sh[t] = v;
    __syncthreads();
#pragma unroll
    for (int o = 1; o < SCAN_BLK; o <<= 1) {
        int add = (t >= o) ? sh[t - o] : 0;
        __syncthreads();
        sh[t] += add;
        __syncthreads();
    }
    if (i < n) g_off[i] = sh[t] - v;          // exclusive within block
    if (t == SCAN_BLK - 1) g_bsum[blockIdx.x] = sh[t];
}

// scan3 with scan2 folded in: every block redundantly scans the (<=128)
// block sums in smem (cheap), then applies its own prefix. No inter-block
// protocol, no polling.
__global__ __launch_bounds__(SCAN_BLK) void scan3_kernel(int n, int nb) {
    __shared__ int sh[128];
    int t = threadIdx.x;
    if (t < 128) sh[t] = (t < nb) ? g_bsum[t] : 0;
    __syncthreads();
#pragma unroll
    for (int o = 1; o < 128; o <<= 1) {
        int add = (t >= o && t < 128) ? sh[t - o] : 0;
        __syncthreads();
        if (t < 128) sh[t] += add;
        __syncthreads();
    }
    int i = blockIdx.x * SCAN_BLK + t;
    if (i < n) {
        int boff = (blockIdx.x > 0) ? sh[blockIdx.x - 1] : 0;
        int o = g_off[i] + boff;
        g_off[i] = o;
        g_cur[i] = o;
    }
}

// ---------------- scatter edges into CSR (by dst) ----------------
__global__ void csr_kernel(const void* __restrict__ ei, int E) {
    int is64 = block_detect_is64((const int*)ei);
    int i = blockIdx.x * blockDim.x + threadIdx.x;
    if (i >= E) return;
    int s, d;
    if (is64) {
        const long long* p = (const long long*)ei;
        s = (int)p[i];
        d = (int)p[(size_t)E + i];
    } else {
        const int* p = (const int*)ei;
        s = p[i];
        d = p[(size_t)E + i];
    }
    if ((unsigned)s >= (unsigned)N_NODES || (unsigned)d >= (unsigned)N_NODES) return;
    int pos = atomicAdd(&g_cur[d], 1);
    g_csr[pos] = s;
}

// ---------------- HMMA GEMM: g = fp16( dinv * (x @ W^T) ) ----------------
// x rounded to fp16; W split hi+lo fp16 (2 MMAs, same fp32 accumulator).
#define GBM 128
#define GKT 32
#define ST 40   // smem row stride in halfs (bank-permuting)
__global__ __launch_bounds__(256) void gemm_mma_kernel(
    const float* __restrict__ x, const float* __restrict__ W, int N)
{
    __shared__ __half xs[GBM][ST];   // x fp16 [m][k]
    __shared__ __half wh[D][ST];     // W hi   [n][k]
    __shared__ __half wl[D][ST];     // W lo   [n][k]

    const int tid = threadIdx.x;
    const int warpId = tid >> 5;
    const int lane = tid & 31;
    const int rowBase = blockIdx.x * GBM;
    const int warpRow = warpId * 16;
    const int qr = lane >> 2;        // 0..7
    const int qc = (lane & 3) * 2;   // 0,2,4,6

    float c[16][4];
#pragma unroll
    for (int t = 0; t < 16; t++)
#pragma unroll
        for (int j = 0; j < 4; j++) c[t][j] = 0.0f;

    for (int kt = 0; kt < D; kt += GKT) {
#pragma unroll
        for (int it = 0; it < 4; it++) {
            int i = tid + it * 256;           // 0..1023 float4 slots
            int m = i >> 3;
            int kq = i & 7;
            float4 v = make_float4(0.f, 0.f, 0.f, 0.f);
            int row = rowBase + m;
            if (row < N)
                v = *(const float4*)(x + (size_t)row * D + kt + kq * 4);
            __half2 p0 = __floats2half2_rn(v.x, v.y);
            __half2 p1 = __floats2half2_rn(v.z, v.w);
            *(__half2*)&xs[m][kq * 4]     = p0;
            *(__half2*)&xs[m][kq * 4 + 2] = p1;
        }
#pragma unroll
        for (int it = 0; it < 4; it++) {
            int i = tid + it * 256;
            int n = i >> 3;
            int kq = i & 7;
            float4 v = *(const float4*)(W + (size_t)n * D + kt + kq * 4);
            __half hx = __float2half_rn(v.x);
            __half hy = __float2half_rn(v.y);
            __half hz = __float2half_rn(v.z);
            __half hw = __float2half_rn(v.w);
            __half lx = __float2half_rn(v.x - __half2float(hx));
            __half ly = __float2half_rn(v.y - __half2float(hy));
            __half lz = __float2half_rn(v.z - __half2float(hz));
            __half lw = __float2half_rn(v.w - __half2float(hw));
            *(__half2*)&wh[n][kq * 4]     = __halves2half2(hx, hy);
            *(__half2*)&wh[n][kq * 4 + 2] = __halves2half2(hz, hw);
            *(__half2*)&wl[n][kq * 4]     = __halves2half2(lx, ly);
            *(__half2*)&wl[n][kq * 4 + 2] = __halves2half2(lz, lw);
        }
        __syncthreads();

#pragma unroll
        for (int k0 = 0; k0 < GKT; k0 += 16) {
            int ar = warpRow + qr;
            int ac = k0 + qc;
            unsigned a0 = *(const unsigned*)&xs[ar][ac];
            unsigned a1 = *(const unsigned*)&xs[ar + 8][ac];
            unsigned a2 = *(const unsigned*)&xs[ar][ac + 8];
            unsigned a3 = *(const unsigned*)&xs[ar + 8][ac + 8];
#pragma unroll
            for (int t = 0; t < 16; t++) {
                int bn = t * 8 + qr;
                unsigned bh0 = *(const unsigned*)&wh[bn][ac];
                unsigned bh1 = *(const unsigned*)&wh[bn][ac + 8];
                unsigned bl0 = *(const unsigned*)&wl[bn][ac];
                unsigned bl1 = *(const unsigned*)&wl[bn][ac + 8];
                mma16816(c[t], a0, a1, a2, a3, bh0, bh1);
                mma16816(c[t], a0, a1, a2, a3, bl0, bl1);
            }
        }
        __syncthreads();
    }

    // epilogue: scale by dinv, convert to fp16 pairs, store
    int r0 = rowBase + warpRow + qr;
    int r1 = r0 + 8;
    float d0 = (r0 < N) ? rsqrtf((float)g_deg[r0] + 1.0f) : 0.0f;
    float d1 = (r1 < N) ? rsqrtf((float)g_deg[r1] + 1.0f) : 0.0f;
    unsigned* gout = (unsigned*)g_gh;          // 64 half2 per row
#pragma unroll
    for (int t = 0; t < 16; t++) {
        int colp = t * 4 + (lane & 3);         // half2 index within row
        if (r0 < N) {
            __half2 h = __floats2half2_rn(c[t][0] * d0, c[t][1] * d0);
            gout[(size_t)r0 * 64 + colp] = *(unsigned*)&h;
        }
        if (r1 < N) {
            __half2 h = __floats2half2_rn(c[t][2] * d1, c[t][3] * d1);
            gout[(size_t)r1 * 64 + colp] = *(unsigned*)&h;
        }
    }
}

// ---------------- aggregate + epilogue: warp per node, MLP=8, fp16 gather ----
__device__ __forceinline__ void acc_u2(float& a0, float& a1, float& a2, float& a3,
                                       uint2 u) {
    float2 p = __half22float2(*(__half2*)&u.x);
    float2 q = __half22float2(*(__half2*)&u.y);
    a0 += p.x; a1 += p.y; a2 += q.x; a3 += q.y;
}

__global__ __launch_bounds__(256) void agg_kernel(
    const float* __restrict__ b, float* __restrict__ out, int N)
{
    int w = (blockIdx.x * blockDim.x + threadIdx.x) >> 5;
    int lane = threadIdx.x & 31;
    if (w >= N) return;

    int deg = g_deg[w];
    int e = g_off[w];
    float dinv = rsqrtf((float)deg + 1.0f);

    float a0 = 0.f, a1 = 0.f, a2 = 0.f, a3 = 0.f;
    acc_u2(a0, a1, a2, a3, g_gh[(size_t)w * 32 + lane]);   // self loop

    int cnt = deg;
    while (cnt >= 8) {
        int s[8];
#pragma unroll
        for (int u = 0; u < 8; u++) s[u] = __ldg(&g_csr[e + u]);
        uint2 v[8];
#pragma unroll
        for (int u = 0; u < 8; u++) v[u] = g_gh[(size_t)s[u] * 32 + lane];
#pragma unroll
        for (int u = 0; u < 8; u++) acc_u2(a0, a1, a2, a3, v[u]);
        e += 8; cnt -= 8;
    }
    if (cnt >= 4) {
        int s0 = __ldg(&g_csr[e + 0]);
        int s1 = __ldg(&g_csr[e + 1]);
        int s2 = __ldg(&g_csr[e + 2]);
        int s3 = __ldg(&g_csr[e + 3]);
        uint2 v0 = g_gh[(size_t)s0 * 32 + lane];
        uint2 v1 = g_gh[(size_t)s1 * 32 + lane];
        uint2 v2 = g_gh[(size_t)s2 * 32 + lane];
        uint2 v3 = g_gh[(size_t)s3 * 32 + lane];
        acc_u2(a0, a1, a2, a3, v0);
        acc_u2(a0, a1, a2, a3, v1);
        acc_u2(a0, a1, a2, a3, v2);
        acc_u2(a0, a1, a2, a3, v3);
        e += 4; cnt -= 4;
    }
    while (cnt > 0) {
        int s = __ldg(&g_csr[e]);
        acc_u2(a0, a1, a2, a3, g_gh[(size_t)s * 32 + lane]);
        e++; cnt--;
    }

    float4 bb = *(const float4*)(b + lane * 4);
    float4 o;
    o.x = fmaxf(fmaf(a0, dinv, bb.x), 0.0f);
    o.y = fmaxf(fmaf(a1, dinv, bb.y), 0.0f);
    o.z = fmaxf(fmaf(a2, dinv, bb.z), 0.0f);
    o.w = fmaxf(fmaf(a3, dinv, bb.w), 0.0f);
    *(float4*)(out + (size_t)w * D + lane * 4) = o;
}

// ---------------- launch ----------------
extern "C" void kernel_launch(void* const* d_in, const int* in_sizes, int n_in,
                              void* d_out, int out_size)
{
    const float* x  = (const float*)d_in[0];
    const void*  ei = d_in[1];                 // [2, E], int64 OR int32 (detected)
    const float* W  = (const float*)d_in[2];
    const float* b  = (const float*)d_in[3];
    float* out = (float*)d_out;

    const int N = in_sizes[0] / D;
    const int E = in_sizes[1] / 2;
    const int NB = (N + SCAN_BLK - 1) / SCAN_BLK;

    zero_deg_kernel<<<(N + 255) / 256, 256>>>(N);
    deg_kernel<<<(E + 255) / 256, 256>>>(ei, E);
    scan1_kernel<<<NB, SCAN_BLK>>>(N);
    scan3_kernel<<<NB, SCAN_BLK>>>(N, NB);
    csr_kernel<<<(E + 255) / 256, 256>>>(ei, E);
    gemm_mma_kernel<<<(N + GBM - 1) / GBM, 256>>>(x, W, N);
    agg_kernel<<<(N * 32 + 255) / 256, 256>>>(b, out, N);
}

// round 16
// speedup vs baseline: 3.6928x; 1.0785x over previous
#include <cuda_runtime.h>
#include <cuda_fp16.h>
#include <cstdint>

#define N_NODES 100000
#define MAX_EDGES 1700000
#define D 128
#define SCAN_BLK 1024

// ---------------- scratch ----------------
// g stored as fp16 (dinv-scaled xW^T): row = 128 halfs = 256B = 32 uint2
__device__ uint2  g_gh[(size_t)N_NODES * 32];
__device__ int    g_deg[N_NODES];                    // in-degree per dst (edges only)
__device__ int    g_off[N_NODES];                    // CSR exclusive offsets
__device__ int    g_cur[N_NODES];                    // scatter cursors
__device__ int    g_csr[MAX_EDGES];                  // src index per CSR slot
__device__ int    g_bsum[128];                       // per-block scan sums

// ---------------- helpers ----------------
__device__ __forceinline__ int block_detect_is64(const int* ei32) {
    int nz = 0;
    if (threadIdx.x < 64) nz = (ei32[2 * threadIdx.x + 1] != 0);
    return !__syncthreads_or(nz);
}

__device__ __forceinline__ void mma16816(float* c,
    unsigned a0, unsigned a1, unsigned a2, unsigned a3,
    unsigned b0, unsigned b1)
{
    asm volatile(
        "mma.sync.aligned.m16n8k16.row.col.f32.f16.f16.f32 "
        "{%0,%1,%2,%3}, {%4,%5,%6,%7}, {%8,%9}, {%0,%1,%2,%3};"
        : "+f"(c[0]), "+f"(c[1]), "+f"(c[2]), "+f"(c[3])
        : "r"(a0), "r"(a1), "r"(a2), "r"(a3), "r"(b0), "r"(b1));
}

// ---------------- kernels ----------------
__global__ void zero_deg_kernel(int n) {
    int i = blockIdx.x * blockDim.x + threadIdx.x;
    if (i < n) g_deg[i] = 0;
}

__global__ void deg_kernel(const void* __restrict__ ei, int E) {
    int is64 = block_detect_is64((const int*)ei);
    int i = blockIdx.x * blockDim.x + threadIdx.x;
    if (i >= E) return;
    int d;
    if (is64) d = (int)((const long long*)ei)[(size_t)E + i];
    else      d = ((const int*)ei)[(size_t)E + i];
    if ((unsigned)d < (unsigned)N_NODES) atomicAdd(&g_deg[d], 1);
}

// ---------------- exclusive scan of g_deg -> g_off (2 kernels, coalesced) ----
__global__ void scan1_kernel(int n) {
    __shared__ int sh[SCAN_BLK];
    int t = threadIdx.x;
    int i = blockIdx.x * SCAN_BLK + t;
    int v = (i < n) ? g_deg[i] : 0;
    sh[t] = v;
    __syncthreads();
#pragma unroll
    for (int o = 1; o < SCAN_BLK; o <<= 1) {
        int add = (t >= o) ? sh[t - o] : 0;
        __syncthreads();
        sh[t] += add;
        __syncthreads();
    }
    if (i < n) g_off[i] = sh[t] - v;          // exclusive within block
    if (t == SCAN_BLK - 1) g_bsum[blockIdx.x] = sh[t];
}

// scan3 with scan2 folded in: every block redundantly scans the (<=128)
// block sums in smem, then applies its own prefix. No inter-block polling.
__global__ __launch_bounds__(SCAN_BLK) void scan3_kernel(int n, int nb) {
    __shared__ int sh[128];
    int t = threadIdx.x;
    if (t < 128) sh[t] = (t < nb) ? g_bsum[t] : 0;
    __syncthreads();
#pragma unroll
    for (int o = 1; o < 128; o <<= 1) {
        int add = (t >= o && t < 128) ? sh[t - o] : 0;
        __syncthreads();
        if (t < 128) sh[t] += add;
        __syncthreads();
    }
    int i = blockIdx.x * SCAN_BLK + t;
    if (i < n) {
        int boff = (blockIdx.x > 0) ? sh[blockIdx.x - 1] : 0;
        int o = g_off[i] + boff;
        g_off[i] = o;
        g_cur[i] = o;
    }
}

// ---------------- scatter edges into CSR (by dst) ----------------
__global__ void csr_kernel(const void* __restrict__ ei, int E) {
    int is64 = block_detect_is64((const int*)ei);
    int i = blockIdx.x * blockDim.x + threadIdx.x;
    if (i >= E) return;
    int s, d;
    if (is64) {
        const long long* p = (const long long*)ei;
        s = (int)p[i];
        d = (int)p[(size_t)E + i];
    } else {
        const int* p = (const int*)ei;
        s = p[i];
        d = p[(size_t)E + i];
    }
    if ((unsigned)s >= (unsigned)N_NODES || (unsigned)d >= (unsigned)N_NODES) return;
    int pos = atomicAdd(&g_cur[d], 1);
    g_csr[pos] = s;
}

// ---------------- HMMA GEMM: g = fp16( dinv * (x @ W^T) ) ----------------
// x rounded to fp16; W split hi+lo fp16 (2 MMAs, same fp32 accumulator).
#define GBM 128
#define GKT 32
#define ST 40   // smem row stride in halfs (bank-permuting)
__global__ __launch_bounds__(256) void gemm_mma_kernel(
    const float* __restrict__ x, const float* __restrict__ W, int N)
{
    __shared__ __half xs[GBM][ST];   // x fp16 [m][k]
    __shared__ __half wh[D][ST];     // W hi   [n][k]
    __shared__ __half wl[D][ST];     // W lo   [n][k]

    const int tid = threadIdx.x;
    const int warpId = tid >> 5;
    const int lane = tid & 31;
    const int rowBase = blockIdx.x * GBM;
    const int warpRow = warpId * 16;
    const int qr = lane >> 2;        // 0..7
    const int qc = (lane & 3) * 2;   // 0,2,4,6

    float c[16][4];
#pragma unroll
    for (int t = 0; t < 16; t++)
#pragma unroll
        for (int j = 0; j < 4; j++) c[t][j] = 0.0f;

    for (int kt = 0; kt < D; kt += GKT) {
#pragma unroll
        for (int it = 0; it < 4; it++) {
            int i = tid + it * 256;           // 0..1023 float4 slots
            int m = i >> 3;
            int kq = i & 7;
            float4 v = make_float4(0.f, 0.f, 0.f, 0.f);
            int row = rowBase + m;
            if (row < N)
                v = *(const float4*)(x + (size_t)row * D + kt + kq * 4);
            __half2 p0 = __floats2half2_rn(v.x, v.y);
            __half2 p1 = __floats2half2_rn(v.z, v.w);
            *(__half2*)&xs[m][kq * 4]     = p0;
            *(__half2*)&xs[m][kq * 4 + 2] = p1;
        }
#pragma unroll
        for (int it = 0; it < 4; it++) {
            int i = tid + it * 256;
            int n = i >> 3;
            int kq = i & 7;
            float4 v = *(const float4*)(W + (size_t)n * D + kt + kq * 4);
            __half hx = __float2half_rn(v.x);
            __half hy = __float2half_rn(v.y);
            __half hz = __float2half_rn(v.z);
            __half hw = __float2half_rn(v.w);
            __half lx = __float2half_rn(v.x - __half2float(hx));
            __half ly = __float2half_rn(v.y - __half2float(hy));
            __half lz = __float2half_rn(v.z - __half2float(hz));
            __half lw = __float2half_rn(v.w - __half2float(hw));
            *(__half2*)&wh[n][kq * 4]     = __halves2half2(hx, hy);
            *(__half2*)&wh[n][kq * 4 + 2] = __halves2half2(hz, hw);
            *(__half2*)&wl[n][kq * 4]     = __halves2half2(lx, ly);
            *(__half2*)&wl[n][kq * 4 + 2] = __halves2half2(lz, lw);
        }
        __syncthreads();

#pragma unroll
        for (int k0 = 0; k0 < GKT; k0 += 16) {
            int ar = warpRow + qr;
            int ac = k0 + qc;
            unsigned a0 = *(const unsigned*)&xs[ar][ac];
            unsigned a1 = *(const unsigned*)&xs[ar + 8][ac];
            unsigned a2 = *(const unsigned*)&xs[ar][ac + 8];
            unsigned a3 = *(const unsigned*)&xs[ar + 8][ac + 8];
#pragma unroll
            for (int t = 0; t < 16; t++) {
                int bn = t * 8 + qr;
                unsigned bh0 = *(const unsigned*)&wh[bn][ac];
                unsigned bh1 = *(const unsigned*)&wh[bn][ac + 8];
                unsigned bl0 = *(const unsigned*)&wl[bn][ac];
                unsigned bl1 = *(const unsigned*)&wl[bn][ac + 8];
                mma16816(c[t], a0, a1, a2, a3, bh0, bh1);
                mma16816(c[t], a0, a1, a2, a3, bl0, bl1);
            }
        }
        __syncthreads();
    }

    // epilogue: scale by dinv, convert to fp16 pairs, store
    int r0 = rowBase + warpRow + qr;
    int r1 = r0 + 8;
    float d0 = (r0 < N) ? rsqrtf((float)g_deg[r0] + 1.0f) : 0.0f;
    float d1 = (r1 < N) ? rsqrtf((float)g_deg[r1] + 1.0f) : 0.0f;
    unsigned* gout = (unsigned*)g_gh;          // 64 half2 per row
#pragma unroll
    for (int t = 0; t < 16; t++) {
        int colp = t * 4 + (lane & 3);         // half2 index within row
        if (r0 < N) {
            __half2 h = __floats2half2_rn(c[t][0] * d0, c[t][1] * d0);
            gout[(size_t)r0 * 64 + colp] = *(unsigned*)&h;
        }
        if (r1 < N) {
            __half2 h = __floats2half2_rn(c[t][2] * d1, c[t][3] * d1);
            gout[(size_t)r1 * 64 + colp] = *(unsigned*)&h;
        }
    }
}

// ---------------- aggregate + epilogue: warp per node, MLP=8, fp16 gather ----
__device__ __forceinline__ void acc_u2(float& a0, float& a1, float& a2, float& a3,
                                       uint2 u) {
    float2 p = __half22float2(*(__half2*)&u.x);
    float2 q = __half22float2(*(__half2*)&u.y);
    a0 += p.x; a1 += p.y; a2 += q.x; a3 += q.y;
}

__global__ __launch_bounds__(256) void agg_kernel(
    const float* __restrict__ b, float* __restrict__ out, int N)
{
    int w = (blockIdx.x * blockDim.x + threadIdx.x) >> 5;
    int lane = threadIdx.x & 31;
    if (w >= N) return;

    int deg = g_deg[w];
    int e = g_off[w];
    float dinv = rsqrtf((float)deg + 1.0f);

    float a0 = 0.f, a1 = 0.f, a2 = 0.f, a3 = 0.f;
    acc_u2(a0, a1, a2, a3, g_gh[(size_t)w * 32 + lane]);   // self loop

    int cnt = deg;
    while (cnt >= 8) {
        int s[8];
#pragma unroll
        for (int u = 0; u < 8; u++) s[u] = __ldg(&g_csr[e + u]);
        uint2 v[8];
#pragma unroll
        for (int u = 0; u < 8; u++) v[u] = g_gh[(size_t)s[u] * 32 + lane];
#pragma unroll
        for (int u = 0; u < 8; u++) acc_u2(a0, a1, a2, a3, v[u]);
        e += 8; cnt -= 8;
    }
    if (cnt >= 4) {
        int s0 = __ldg(&g_csr[e + 0]);
        int s1 = __ldg(&g_csr[e + 1]);
        int s2 = __ldg(&g_csr[e + 2]);
        int s3 = __ldg(&g_csr[e + 3]);
        uint2 v0 = g_gh[(size_t)s0 * 32 + lane];
        uint2 v1 = g_gh[(size_t)s1 * 32 + lane];
        uint2 v2 = g_gh[(size_t)s2 * 32 + lane];
        uint2 v3 = g_gh[(size_t)s3 * 32 + lane];
        acc_u2(a0, a1, a2, a3, v0);
        acc_u2(a0, a1, a2, a3, v1);
        acc_u2(a0, a1, a2, a3, v2);
        acc_u2(a0, a1, a2, a3, v3);
        e += 4; cnt -= 4;
    }
    while (cnt > 0) {
        int s = __ldg(&g_csr[e]);
        acc_u2(a0, a1, a2, a3, g_gh[(size_t)s * 32 + lane]);
        e++; cnt--;
    }

    float4 bb = *(const float4*)(b + lane * 4);
    float4 o;
    o.x = fmaxf(fmaf(a0, dinv, bb.x), 0.0f);
    o.y = fmaxf(fmaf(a1, dinv, bb.y), 0.0f);
    o.z = fmaxf(fmaf(a2, dinv, bb.z), 0.0f);
    o.w = fmaxf(fmaf(a3, dinv, bb.w), 0.0f);
    *(float4*)(out + (size_t)w * D + lane * 4) = o;
}

// ---------------- launch ----------------
extern "C" void kernel_launch(void* const* d_in, const int* in_sizes, int n_in,
                              void* d_out, int out_size)
{
    const float* x  = (const float*)d_in[0];
    const void*  ei = d_in[1];                 // [2, E], int64 OR int32 (detected)
    const float* W  = (const float*)d_in[2];
    const float* b  = (const float*)d_in[3];
    float* out = (float*)d_out;

    const int N = in_sizes[0] / D;
    const int E = in_sizes[1] / 2;
    const int NB = (N + SCAN_BLK - 1) / SCAN_BLK;

    static cudaStream_t s2 = nullptr;
    static cudaEvent_t evDeg = nullptr, evJoin = nullptr;
    if (s2 == nullptr) {
        cudaStreamCreateWithFlags(&s2, cudaStreamNonBlocking);
        cudaEventCreateWithFlags(&evDeg, cudaEventDisableTiming);
        cudaEventCreateWithFlags(&evJoin, cudaEventDisableTiming);
    }

    // Main stream: degree histogram first (GEMM epilogue needs g_deg).
    zero_deg_kernel<<<(N + 255) / 256, 256>>>(N);
    deg_kernel<<<(E + 255) / 256, 256>>>(ei, E);
    cudaEventRecord(evDeg, 0);

    // Side stream: GEMM overlaps scan + csr.
    cudaStreamWaitEvent(s2, evDeg, 0);
    gemm_mma_kernel<<<(N + GBM - 1) / GBM, 256, 0, s2>>>(x, W, N);
    cudaEventRecord(evJoin, s2);

    // Main stream: scan + CSR scatter.
    scan1_kernel<<<NB, SCAN_BLK>>>(N);
    scan3_kernel<<<NB, SCAN_BLK>>>(N, NB);
    csr_kernel<<<(E + 255) / 256, 256>>>(ei, E);

    // Join, then aggregate.
    cudaStreamWaitEvent(0, evJoin, 0);
    agg_kernel<<<(N * 32 + 255) / 256, 256>>>(b, out, N);
}